// round 1
// baseline (speedup 1.0000x reference)
#include <cuda_runtime.h>
#include <cuda_bf16.h>
#include <cstddef>

// Problem constants
#define BATCH 8
#define CC    512
#define LL    2048
#define NGROUPS 32
#define CPG   (CC / NGROUPS)      // 16 channels per group
#define GROUP_ELEMS (CPG * LL)    // 32768
#define EPS   1e-5f

// ---------------------------------------------------------------------------
// Device scratch (static globals: allowed; no runtime allocation)
// ---------------------------------------------------------------------------
__device__ float g_h[(size_t)BATCH * CC * LL];        // groupnorm output
__device__ float g_q[(size_t)BATCH * CC * LL];
__device__ float g_k[(size_t)BATCH * CC * LL];
__device__ float g_v[(size_t)BATCH * CC * LL];
__device__ float g_w[(size_t)BATCH * LL * LL];        // attention scores (134 MB)
__device__ float g_a[(size_t)BATCH * CC * LL];        // attn output (pre-proj)

// ---------------------------------------------------------------------------
// Reductions
// ---------------------------------------------------------------------------
__device__ __forceinline__ float warp_sum(float v) {
    #pragma unroll
    for (int o = 16; o > 0; o >>= 1) v += __shfl_xor_sync(0xffffffffu, v, o);
    return v;
}
__device__ __forceinline__ float warp_max(float v) {
    #pragma unroll
    for (int o = 16; o > 0; o >>= 1) v = fmaxf(v, __shfl_xor_sync(0xffffffffu, v, o));
    return v;
}

// ---------------------------------------------------------------------------
// Kernel 1: GroupNorm.  grid = B*NGROUPS blocks, 512 threads.
// ---------------------------------------------------------------------------
__global__ void gn_kernel(const float* __restrict__ x,
                          const float* __restrict__ gamma,
                          const float* __restrict__ beta,
                          float* __restrict__ h) {
    const int bg = blockIdx.x;
    const int b  = bg / NGROUPS;
    const int g  = bg % NGROUPS;
    const size_t base = ((size_t)b * CC + (size_t)g * CPG) * LL;
    const float* xp = x + base;

    float s = 0.f, s2 = 0.f;
    for (int i = threadIdx.x; i < GROUP_ELEMS; i += blockDim.x) {
        float v = xp[i];
        s  += v;
        s2 += v * v;
    }
    __shared__ float red1[16], red2[16];
    s  = warp_sum(s);
    s2 = warp_sum(s2);
    const int lane = threadIdx.x & 31, wid = threadIdx.x >> 5;
    if (lane == 0) { red1[wid] = s; red2[wid] = s2; }
    __syncthreads();
    if (wid == 0) {
        s  = (lane < 16) ? red1[lane] : 0.f;
        s2 = (lane < 16) ? red2[lane] : 0.f;
        s  = warp_sum(s);
        s2 = warp_sum(s2);
        if (lane == 0) { red1[0] = s; red2[0] = s2; }
    }
    __syncthreads();
    const float mean = red1[0] * (1.0f / GROUP_ELEMS);
    const float var  = red2[0] * (1.0f / GROUP_ELEMS) - mean * mean;
    const float inv  = rsqrtf(var + EPS);

    float* hp = h + base;
    for (int i = threadIdx.x; i < GROUP_ELEMS; i += blockDim.x) {
        int c = g * CPG + i / LL;
        hp[i] = (xp[i] - mean) * inv * gamma[c] + beta[c];
    }
}

// ---------------------------------------------------------------------------
// Tiled SGEMM config: 128x128 tile, BK=8, 256 threads, 8x8 per thread.
// Shared arrays padded to 132 to avoid store-side bank conflicts.
// ---------------------------------------------------------------------------
#define BM 128
#define BN 128
#define BK 8
#define SPAD 132

// Kernel 2: out[b,o,l] = sum_c W[o,c] * H[b,c,l] + bias[o]  (+ residual X)
// grid = (L/BN, C/BM, B); also used for final projection with X != nullptr.
__global__ __launch_bounds__(256, 2)
void gemm_wh(const float* __restrict__ W, const float* __restrict__ bias,
             const float* __restrict__ H, float* __restrict__ out,
             const float* __restrict__ X) {
    const int b = blockIdx.z;
    const float* Hb = H + (size_t)b * CC * LL;
    float* Ob = out + (size_t)b * CC * LL;

    __shared__ float As[BK][SPAD];   // As[k][m] = W[rowBase+m, k0+k]
    __shared__ float Bs[BK][SPAD];   // Bs[k][n] = H[k0+k, colBase+n]
    const int tid = threadIdx.x;
    const int tx = tid & 15, ty = tid >> 4;
    const int rowBase = blockIdx.y * BM;   // o
    const int colBase = blockIdx.x * BN;   // l

    float acc[8][8];
    #pragma unroll
    for (int i = 0; i < 8; i++)
        #pragma unroll
        for (int j = 0; j < 8; j++) acc[i][j] = 0.f;

    for (int k0 = 0; k0 < CC; k0 += BK) {
        #pragma unroll
        for (int p = 0; p < 4; p++) {
            int t = tid + p * 256;
            int m = t >> 3, kk = t & 7;
            As[kk][m] = W[(size_t)(rowBase + m) * CC + k0 + kk];
        }
        #pragma unroll
        for (int p = 0; p < 4; p++) {
            int t = tid + p * 256;
            int n = t & 127, kk = t >> 7;
            Bs[kk][n] = Hb[(size_t)(k0 + kk) * LL + colBase + n];
        }
        __syncthreads();
        #pragma unroll
        for (int kk = 0; kk < BK; kk++) {
            float ra[8], rb[8];
            #pragma unroll
            for (int i = 0; i < 8; i++) ra[i] = As[kk][ty * 8 + i];
            #pragma unroll
            for (int j = 0; j < 8; j++) rb[j] = Bs[kk][tx * 8 + j];
            #pragma unroll
            for (int i = 0; i < 8; i++)
                #pragma unroll
                for (int j = 0; j < 8; j++) acc[i][j] = fmaf(ra[i], rb[j], acc[i][j]);
        }
        __syncthreads();
    }
    #pragma unroll
    for (int i = 0; i < 8; i++) {
        int o = rowBase + ty * 8 + i;
        float bv = bias[o];
        #pragma unroll
        for (int j = 0; j < 8; j++) {
            int l = colBase + tx * 8 + j;
            float v = acc[i][j] + bv;
            if (X) v += X[((size_t)b * CC + o) * LL + l];
            Ob[(size_t)o * LL + l] = v;
        }
    }
}

// Kernel 3: w[b,i,j] = scale * sum_c q[b,c,i] * k[b,c,j]
// grid = (L/BN, L/BM, B)
__global__ __launch_bounds__(256, 2)
void gemm_qk(const float* __restrict__ q, const float* __restrict__ k,
             float* __restrict__ w, float scale) {
    const int b = blockIdx.z;
    const float* Qb = q + (size_t)b * CC * LL;
    const float* Kb = k + (size_t)b * CC * LL;
    float* Wb = w + (size_t)b * LL * LL;

    __shared__ float As[BK][SPAD];   // As[c][i]
    __shared__ float Bs[BK][SPAD];   // Bs[c][j]
    const int tid = threadIdx.x;
    const int tx = tid & 15, ty = tid >> 4;
    const int rowBase = blockIdx.y * BM;   // i
    const int colBase = blockIdx.x * BN;   // j

    float acc[8][8];
    #pragma unroll
    for (int i = 0; i < 8; i++)
        #pragma unroll
        for (int j = 0; j < 8; j++) acc[i][j] = 0.f;

    for (int c0 = 0; c0 < CC; c0 += BK) {
        #pragma unroll
        for (int p = 0; p < 4; p++) {
            int t = tid + p * 256;
            int n = t & 127, kk = t >> 7;
            As[kk][n] = Qb[(size_t)(c0 + kk) * LL + rowBase + n];
            Bs[kk][n] = Kb[(size_t)(c0 + kk) * LL + colBase + n];
        }
        __syncthreads();
        #pragma unroll
        for (int kk = 0; kk < BK; kk++) {
            float ra[8], rb[8];
            #pragma unroll
            for (int i = 0; i < 8; i++) ra[i] = As[kk][ty * 8 + i];
            #pragma unroll
            for (int j = 0; j < 8; j++) rb[j] = Bs[kk][tx * 8 + j];
            #pragma unroll
            for (int i = 0; i < 8; i++)
                #pragma unroll
                for (int j = 0; j < 8; j++) acc[i][j] = fmaf(ra[i], rb[j], acc[i][j]);
        }
        __syncthreads();
    }
    #pragma unroll
    for (int i = 0; i < 8; i++) {
        int ii = rowBase + ty * 8 + i;
        #pragma unroll
        for (int j = 0; j < 8; j++) {
            int jj = colBase + tx * 8 + j;
            Wb[(size_t)ii * LL + jj] = acc[i][j] * scale;
        }
    }
}

// Kernel 4: row softmax over w[b,i,:].  grid = B*L blocks, 256 threads.
__global__ void softmax_kernel(float* __restrict__ w) {
    float* p = w + (size_t)blockIdx.x * LL;
    __shared__ float red[8];
    const int lane = threadIdx.x & 31, wid = threadIdx.x >> 5;

    float m = -1e30f;
    for (int i = threadIdx.x; i < LL; i += 256) m = fmaxf(m, p[i]);
    m = warp_max(m);
    if (lane == 0) red[wid] = m;
    __syncthreads();
    if (wid == 0) {
        m = (lane < 8) ? red[lane] : -1e30f;
        m = warp_max(m);
        if (lane == 0) red[0] = m;
    }
    __syncthreads();
    m = red[0];
    __syncthreads();

    float s = 0.f;
    for (int i = threadIdx.x; i < LL; i += 256) {
        float e = __expf(p[i] - m);
        p[i] = e;
        s += e;
    }
    s = warp_sum(s);
    if (lane == 0) red[wid] = s;
    __syncthreads();
    if (wid == 0) {
        s = (lane < 8) ? red[lane] : 0.f;
        s = warp_sum(s);
        if (lane == 0) red[0] = s;
    }
    __syncthreads();
    const float inv = 1.0f / red[0];
    for (int i = threadIdx.x; i < LL; i += 256) p[i] *= inv;
}

// Kernel 5: a[b,c,i] = sum_j w[b,i,j] * v[b,c,j]
// grid = (L/BN (i), C/BM (c), B)
__global__ __launch_bounds__(256, 2)
void gemm_av(const float* __restrict__ w, const float* __restrict__ v,
             float* __restrict__ a) {
    const int b = blockIdx.z;
    const float* Wb = w + (size_t)b * LL * LL;
    const float* Vb = v + (size_t)b * CC * LL;
    float* Ab = a + (size_t)b * CC * LL;

    __shared__ float As[BK][SPAD];   // As[j][c] = V[rowBase+c, j0+j]
    __shared__ float Bs[BK][SPAD];   // Bs[j][i] = w[colBase+i, j0+j]
    const int tid = threadIdx.x;
    const int tx = tid & 15, ty = tid >> 4;
    const int rowBase = blockIdx.y * BM;   // c
    const int colBase = blockIdx.x * BN;   // i

    float acc[8][8];
    #pragma unroll
    for (int i = 0; i < 8; i++)
        #pragma unroll
        for (int j = 0; j < 8; j++) acc[i][j] = 0.f;

    for (int j0 = 0; j0 < LL; j0 += BK) {
        #pragma unroll
        for (int p = 0; p < 4; p++) {
            int t = tid + p * 256;
            int m = t >> 3, kk = t & 7;
            As[kk][m] = Vb[(size_t)(rowBase + m) * LL + j0 + kk];
        }
        #pragma unroll
        for (int p = 0; p < 4; p++) {
            int t = tid + p * 256;
            int n = t >> 3, kk = t & 7;
            Bs[kk][n] = Wb[(size_t)(colBase + n) * LL + j0 + kk];
        }
        __syncthreads();
        #pragma unroll
        for (int kk = 0; kk < BK; kk++) {
            float ra[8], rb[8];
            #pragma unroll
            for (int i = 0; i < 8; i++) ra[i] = As[kk][ty * 8 + i];
            #pragma unroll
            for (int j = 0; j < 8; j++) rb[j] = Bs[kk][tx * 8 + j];
            #pragma unroll
            for (int i = 0; i < 8; i++)
                #pragma unroll
                for (int j = 0; j < 8; j++) acc[i][j] = fmaf(ra[i], rb[j], acc[i][j]);
        }
        __syncthreads();
    }
    #pragma unroll
    for (int i = 0; i < 8; i++) {
        int c = rowBase + ty * 8 + i;
        #pragma unroll
        for (int j = 0; j < 8; j++) {
            int ii = colBase + tx * 8 + j;
            Ab[(size_t)c * LL + ii] = acc[i][j];
        }
    }
}

// ---------------------------------------------------------------------------
// Launch
// ---------------------------------------------------------------------------
extern "C" void kernel_launch(void* const* d_in, const int* in_sizes, int n_in,
                              void* d_out, int out_size) {
    const float* x        = (const float*)d_in[0];
    const float* gn_gamma = (const float*)d_in[1];
    const float* gn_beta  = (const float*)d_in[2];
    const float* Wq = (const float*)d_in[3];
    const float* bq = (const float*)d_in[4];
    const float* Wk = (const float*)d_in[5];
    const float* bk = (const float*)d_in[6];
    const float* Wv = (const float*)d_in[7];
    const float* bv = (const float*)d_in[8];
    const float* Wo = (const float*)d_in[9];
    const float* bo = (const float*)d_in[10];
    float* out = (float*)d_out;

    float *h, *q, *k, *v, *w, *a;
    cudaGetSymbolAddress((void**)&h, g_h);
    cudaGetSymbolAddress((void**)&q, g_q);
    cudaGetSymbolAddress((void**)&k, g_k);
    cudaGetSymbolAddress((void**)&v, g_v);
    cudaGetSymbolAddress((void**)&w, g_w);
    cudaGetSymbolAddress((void**)&a, g_a);

    // 1. GroupNorm
    gn_kernel<<<BATCH * NGROUPS, 512>>>(x, gn_gamma, gn_beta, h);

    // 2. q, k, v projections  (M=C=512, N=L=2048, K=C=512)
    dim3 gproj(LL / BN, CC / BM, BATCH);
    gemm_wh<<<gproj, 256>>>(Wq, bq, h, q, nullptr);
    gemm_wh<<<gproj, 256>>>(Wk, bk, h, k, nullptr);
    gemm_wh<<<gproj, 256>>>(Wv, bv, h, v, nullptr);

    // 3. scores  (M=N=L=2048, K=C=512)
    dim3 gqk(LL / BN, LL / BM, BATCH);
    const float scale = 0.044194173824159216f;   // 1/sqrt(512)
    gemm_qk<<<gqk, 256>>>(q, k, w, scale);

    // 4. softmax over rows
    softmax_kernel<<<BATCH * LL, 256>>>(w);

    // 5. a = attn @ v  (M=C=512, N=L=2048, K=L=2048)
    dim3 gav(LL / BN, CC / BM, BATCH);
    gemm_av<<<gav, 256>>>(w, v, a);

    // 6. out = x + Wo @ a + bo
    gemm_wh<<<gproj, 256>>>(Wo, bo, a, out, x);
}

// round 2
// speedup vs baseline: 1.0003x; 1.0003x over previous
#include <cuda_runtime.h>
#include <cuda_bf16.h>
#include <cstddef>

// Problem constants
#define BATCH 8
#define CC    512
#define LL    2048
#define NGROUPS 32
#define CPG   (CC / NGROUPS)      // 16 channels per group
#define GROUP_ELEMS (CPG * LL)    // 32768
#define EPS   1e-5f

// ---------------------------------------------------------------------------
// Device scratch (static globals: allowed; no runtime allocation)
// ---------------------------------------------------------------------------
__device__ float g_h[(size_t)BATCH * CC * LL];        // groupnorm output
__device__ float g_q[(size_t)BATCH * CC * LL];
__device__ float g_k[(size_t)BATCH * CC * LL];
__device__ float g_v[(size_t)BATCH * CC * LL];
__device__ float g_w[(size_t)BATCH * LL * LL];        // attention scores (134 MB)
__device__ float g_a[(size_t)BATCH * CC * LL];        // attn output (pre-proj)

// ---------------------------------------------------------------------------
// Reductions
// ---------------------------------------------------------------------------
__device__ __forceinline__ float warp_sum(float v) {
    #pragma unroll
    for (int o = 16; o > 0; o >>= 1) v += __shfl_xor_sync(0xffffffffu, v, o);
    return v;
}
__device__ __forceinline__ float warp_max(float v) {
    #pragma unroll
    for (int o = 16; o > 0; o >>= 1) v = fmaxf(v, __shfl_xor_sync(0xffffffffu, v, o));
    return v;
}

// ---------------------------------------------------------------------------
// Kernel 1: GroupNorm.  grid = B*NGROUPS blocks, 512 threads.
// ---------------------------------------------------------------------------
__global__ void gn_kernel(const float* __restrict__ x,
                          const float* __restrict__ gamma,
                          const float* __restrict__ beta,
                          float* __restrict__ h) {
    const int bg = blockIdx.x;
    const int b  = bg / NGROUPS;
    const int g  = bg % NGROUPS;
    const size_t base = ((size_t)b * CC + (size_t)g * CPG) * LL;
    const float* xp = x + base;

    float s = 0.f, s2 = 0.f;
    for (int i = threadIdx.x; i < GROUP_ELEMS; i += blockDim.x) {
        float v = xp[i];
        s  += v;
        s2 += v * v;
    }
    __shared__ float red1[16], red2[16];
    s  = warp_sum(s);
    s2 = warp_sum(s2);
    const int lane = threadIdx.x & 31, wid = threadIdx.x >> 5;
    if (lane == 0) { red1[wid] = s; red2[wid] = s2; }
    __syncthreads();
    if (wid == 0) {
        s  = (lane < 16) ? red1[lane] : 0.f;
        s2 = (lane < 16) ? red2[lane] : 0.f;
        s  = warp_sum(s);
        s2 = warp_sum(s2);
        if (lane == 0) { red1[0] = s; red2[0] = s2; }
    }
    __syncthreads();
    const float mean = red1[0] * (1.0f / GROUP_ELEMS);
    const float var  = red2[0] * (1.0f / GROUP_ELEMS) - mean * mean;
    const float inv  = rsqrtf(var + EPS);

    float* hp = h + base;
    for (int i = threadIdx.x; i < GROUP_ELEMS; i += blockDim.x) {
        int c = g * CPG + i / LL;
        hp[i] = (xp[i] - mean) * inv * gamma[c] + beta[c];
    }
}

// ---------------------------------------------------------------------------
// Tiled SGEMM config: 128x128 tile, BK=8, 256 threads, 8x8 per thread.
// Shared arrays padded to 132 to avoid store-side bank conflicts.
// ---------------------------------------------------------------------------
#define BM 128
#define BN 128
#define BK 8
#define SPAD 132

// Kernel 2: out[b,o,l] = sum_c W[o,c] * H[b,c,l] + bias[o]  (+ residual X)
// grid = (L/BN, C/BM, B); also used for final projection with X != nullptr.
__global__ __launch_bounds__(256, 2)
void gemm_wh(const float* __restrict__ W, const float* __restrict__ bias,
             const float* __restrict__ H, float* __restrict__ out,
             const float* __restrict__ X) {
    const int b = blockIdx.z;
    const float* Hb = H + (size_t)b * CC * LL;
    float* Ob = out + (size_t)b * CC * LL;

    __shared__ float As[BK][SPAD];   // As[k][m] = W[rowBase+m, k0+k]
    __shared__ float Bs[BK][SPAD];   // Bs[k][n] = H[k0+k, colBase+n]
    const int tid = threadIdx.x;
    const int tx = tid & 15, ty = tid >> 4;
    const int rowBase = blockIdx.y * BM;   // o
    const int colBase = blockIdx.x * BN;   // l

    float acc[8][8];
    #pragma unroll
    for (int i = 0; i < 8; i++)
        #pragma unroll
        for (int j = 0; j < 8; j++) acc[i][j] = 0.f;

    for (int k0 = 0; k0 < CC; k0 += BK) {
        #pragma unroll
        for (int p = 0; p < 4; p++) {
            int t = tid + p * 256;
            int m = t >> 3, kk = t & 7;
            As[kk][m] = W[(size_t)(rowBase + m) * CC + k0 + kk];
        }
        #pragma unroll
        for (int p = 0; p < 4; p++) {
            int t = tid + p * 256;
            int n = t & 127, kk = t >> 7;
            Bs[kk][n] = Hb[(size_t)(k0 + kk) * LL + colBase + n];
        }
        __syncthreads();
        #pragma unroll
        for (int kk = 0; kk < BK; kk++) {
            float ra[8], rb[8];
            #pragma unroll
            for (int i = 0; i < 8; i++) ra[i] = As[kk][ty * 8 + i];
            #pragma unroll
            for (int j = 0; j < 8; j++) rb[j] = Bs[kk][tx * 8 + j];
            #pragma unroll
            for (int i = 0; i < 8; i++)
                #pragma unroll
                for (int j = 0; j < 8; j++) acc[i][j] = fmaf(ra[i], rb[j], acc[i][j]);
        }
        __syncthreads();
    }
    #pragma unroll
    for (int i = 0; i < 8; i++) {
        int o = rowBase + ty * 8 + i;
        float bv = bias[o];
        #pragma unroll
        for (int j = 0; j < 8; j++) {
            int l = colBase + tx * 8 + j;
            float v = acc[i][j] + bv;
            if (X) v += X[((size_t)b * CC + o) * LL + l];
            Ob[(size_t)o * LL + l] = v;
        }
    }
}

// Kernel 3: w[b,i,j] = scale * sum_c q[b,c,i] * k[b,c,j]
// grid = (L/BN, L/BM, B)
__global__ __launch_bounds__(256, 2)
void gemm_qk(const float* __restrict__ q, const float* __restrict__ k,
             float* __restrict__ w, float scale) {
    const int b = blockIdx.z;
    const float* Qb = q + (size_t)b * CC * LL;
    const float* Kb = k + (size_t)b * CC * LL;
    float* Wb = w + (size_t)b * LL * LL;

    __shared__ float As[BK][SPAD];   // As[c][i]
    __shared__ float Bs[BK][SPAD];   // Bs[c][j]
    const int tid = threadIdx.x;
    const int tx = tid & 15, ty = tid >> 4;
    const int rowBase = blockIdx.y * BM;   // i
    const int colBase = blockIdx.x * BN;   // j

    float acc[8][8];
    #pragma unroll
    for (int i = 0; i < 8; i++)
        #pragma unroll
        for (int j = 0; j < 8; j++) acc[i][j] = 0.f;

    for (int c0 = 0; c0 < CC; c0 += BK) {
        #pragma unroll
        for (int p = 0; p < 4; p++) {
            int t = tid + p * 256;
            int n = t & 127, kk = t >> 7;
            As[kk][n] = Qb[(size_t)(c0 + kk) * LL + rowBase + n];
            Bs[kk][n] = Kb[(size_t)(c0 + kk) * LL + colBase + n];
        }
        __syncthreads();
        #pragma unroll
        for (int kk = 0; kk < BK; kk++) {
            float ra[8], rb[8];
            #pragma unroll
            for (int i = 0; i < 8; i++) ra[i] = As[kk][ty * 8 + i];
            #pragma unroll
            for (int j = 0; j < 8; j++) rb[j] = Bs[kk][tx * 8 + j];
            #pragma unroll
            for (int i = 0; i < 8; i++)
                #pragma unroll
                for (int j = 0; j < 8; j++) acc[i][j] = fmaf(ra[i], rb[j], acc[i][j]);
        }
        __syncthreads();
    }
    #pragma unroll
    for (int i = 0; i < 8; i++) {
        int ii = rowBase + ty * 8 + i;
        #pragma unroll
        for (int j = 0; j < 8; j++) {
            int jj = colBase + tx * 8 + j;
            Wb[(size_t)ii * LL + jj] = acc[i][j] * scale;
        }
    }
}

// Kernel 4: row softmax over w[b,i,:].  grid = B*L blocks, 256 threads.
__global__ void softmax_kernel(float* __restrict__ w) {
    float* p = w + (size_t)blockIdx.x * LL;
    __shared__ float red[8];
    const int lane = threadIdx.x & 31, wid = threadIdx.x >> 5;

    float m = -1e30f;
    for (int i = threadIdx.x; i < LL; i += 256) m = fmaxf(m, p[i]);
    m = warp_max(m);
    if (lane == 0) red[wid] = m;
    __syncthreads();
    if (wid == 0) {
        m = (lane < 8) ? red[lane] : -1e30f;
        m = warp_max(m);
        if (lane == 0) red[0] = m;
    }
    __syncthreads();
    m = red[0];
    __syncthreads();

    float s = 0.f;
    for (int i = threadIdx.x; i < LL; i += 256) {
        float e = __expf(p[i] - m);
        p[i] = e;
        s += e;
    }
    s = warp_sum(s);
    if (lane == 0) red[wid] = s;
    __syncthreads();
    if (wid == 0) {
        s = (lane < 8) ? red[lane] : 0.f;
        s = warp_sum(s);
        if (lane == 0) red[0] = s;
    }
    __syncthreads();
    const float inv = 1.0f / red[0];
    for (int i = threadIdx.x; i < LL; i += 256) p[i] *= inv;
}

// Kernel 5: a[b,c,i] = sum_j w[b,i,j] * v[b,c,j]
// grid = (L/BN (i), C/BM (c), B)
__global__ __launch_bounds__(256, 2)
void gemm_av(const float* __restrict__ w, const float* __restrict__ v,
             float* __restrict__ a) {
    const int b = blockIdx.z;
    const float* Wb = w + (size_t)b * LL * LL;
    const float* Vb = v + (size_t)b * CC * LL;
    float* Ab = a + (size_t)b * CC * LL;

    __shared__ float As[BK][SPAD];   // As[j][c] = V[rowBase+c, j0+j]
    __shared__ float Bs[BK][SPAD];   // Bs[j][i] = w[colBase+i, j0+j]
    const int tid = threadIdx.x;
    const int tx = tid & 15, ty = tid >> 4;
    const int rowBase = blockIdx.y * BM;   // c
    const int colBase = blockIdx.x * BN;   // i

    float acc[8][8];
    #pragma unroll
    for (int i = 0; i < 8; i++)
        #pragma unroll
        for (int j = 0; j < 8; j++) acc[i][j] = 0.f;

    for (int j0 = 0; j0 < LL; j0 += BK) {
        #pragma unroll
        for (int p = 0; p < 4; p++) {
            int t = tid + p * 256;
            int m = t >> 3, kk = t & 7;
            As[kk][m] = Vb[(size_t)(rowBase + m) * LL + j0 + kk];
        }
        #pragma unroll
        for (int p = 0; p < 4; p++) {
            int t = tid + p * 256;
            int n = t >> 3, kk = t & 7;
            Bs[kk][n] = Wb[(size_t)(colBase + n) * LL + j0 + kk];
        }
        __syncthreads();
        #pragma unroll
        for (int kk = 0; kk < BK; kk++) {
            float ra[8], rb[8];
            #pragma unroll
            for (int i = 0; i < 8; i++) ra[i] = As[kk][ty * 8 + i];
            #pragma unroll
            for (int j = 0; j < 8; j++) rb[j] = Bs[kk][tx * 8 + j];
            #pragma unroll
            for (int i = 0; i < 8; i++)
                #pragma unroll
                for (int j = 0; j < 8; j++) acc[i][j] = fmaf(ra[i], rb[j], acc[i][j]);
        }
        __syncthreads();
    }
    #pragma unroll
    for (int i = 0; i < 8; i++) {
        int c = rowBase + ty * 8 + i;
        #pragma unroll
        for (int j = 0; j < 8; j++) {
            int ii = colBase + tx * 8 + j;
            Ab[(size_t)c * LL + ii] = acc[i][j];
        }
    }
}

// ---------------------------------------------------------------------------
// Launch
// ---------------------------------------------------------------------------
extern "C" void kernel_launch(void* const* d_in, const int* in_sizes, int n_in,
                              void* d_out, int out_size) {
    const float* x        = (const float*)d_in[0];
    const float* gn_gamma = (const float*)d_in[1];
    const float* gn_beta  = (const float*)d_in[2];
    const float* Wq = (const float*)d_in[3];
    const float* bq = (const float*)d_in[4];
    const float* Wk = (const float*)d_in[5];
    const float* bk = (const float*)d_in[6];
    const float* Wv = (const float*)d_in[7];
    const float* bv = (const float*)d_in[8];
    const float* Wo = (const float*)d_in[9];
    const float* bo = (const float*)d_in[10];
    float* out = (float*)d_out;

    float *h, *q, *k, *v, *w, *a;
    cudaGetSymbolAddress((void**)&h, g_h);
    cudaGetSymbolAddress((void**)&q, g_q);
    cudaGetSymbolAddress((void**)&k, g_k);
    cudaGetSymbolAddress((void**)&v, g_v);
    cudaGetSymbolAddress((void**)&w, g_w);
    cudaGetSymbolAddress((void**)&a, g_a);

    // 1. GroupNorm
    gn_kernel<<<BATCH * NGROUPS, 512>>>(x, gn_gamma, gn_beta, h);

    // 2. q, k, v projections  (M=C=512, N=L=2048, K=C=512)
    dim3 gproj(LL / BN, CC / BM, BATCH);
    gemm_wh<<<gproj, 256>>>(Wq, bq, h, q, nullptr);
    gemm_wh<<<gproj, 256>>>(Wk, bk, h, k, nullptr);
    gemm_wh<<<gproj, 256>>>(Wv, bv, h, v, nullptr);

    // 3. scores  (M=N=L=2048, K=C=512)
    dim3 gqk(LL / BN, LL / BM, BATCH);
    const float scale = 0.044194173824159216f;   // 1/sqrt(512)
    gemm_qk<<<gqk, 256>>>(q, k, w, scale);

    // 4. softmax over rows
    softmax_kernel<<<BATCH * LL, 256>>>(w);

    // 5. a = attn @ v  (M=C=512, N=L=2048, K=L=2048)
    dim3 gav(LL / BN, CC / BM, BATCH);
    gemm_av<<<gav, 256>>>(w, v, a);

    // 6. out = x + Wo @ a + bo
    gemm_wh<<<gproj, 256>>>(Wo, bo, a, out, x);
}

// round 3
// speedup vs baseline: 3.1770x; 3.1759x over previous
#include <cuda_runtime.h>
#include <cuda_bf16.h>
#include <cstdint>
#include <cstddef>

// Problem constants
#define BATCH 8
#define CC    512
#define LL    2048
#define NGROUPS 32
#define CPG   (CC / NGROUPS)      // 16
#define GROUP_ELEMS (CPG * LL)    // 32768
#define EPS   1e-5f

// ---------------------------------------------------------------------------
// Device scratch
// ---------------------------------------------------------------------------
__device__ float g_h[(size_t)BATCH * CC * LL];
__device__ float g_q[(size_t)BATCH * CC * LL];
__device__ float g_k[(size_t)BATCH * CC * LL];
__device__ float g_v[(size_t)BATCH * CC * LL];
__device__ float g_w[(size_t)BATCH * LL * LL];
__device__ float g_a[(size_t)BATCH * CC * LL];

// ---------------------------------------------------------------------------
// Helpers
// ---------------------------------------------------------------------------
__device__ __forceinline__ float warp_sum(float v) {
    #pragma unroll
    for (int o = 16; o > 0; o >>= 1) v += __shfl_xor_sync(0xffffffffu, v, o);
    return v;
}
__device__ __forceinline__ float warp_max(float v) {
    #pragma unroll
    for (int o = 16; o > 0; o >>= 1) v = fmaxf(v, __shfl_xor_sync(0xffffffffu, v, o));
    return v;
}
__device__ __forceinline__ float to_tf32(float x) {
    float r;
    asm("cvt.rna.tf32.f32 %0, %1;" : "=f"(r) : "f"(x));
    return r;
}
__device__ __forceinline__ void mma8(float* d, const uint32_t* a, const uint32_t* b) {
    asm volatile(
        "mma.sync.aligned.m16n8k8.row.col.f32.tf32.tf32.f32 "
        "{%0,%1,%2,%3}, {%4,%5,%6,%7}, {%8,%9}, {%0,%1,%2,%3};\n"
        : "+f"(d[0]), "+f"(d[1]), "+f"(d[2]), "+f"(d[3])
        : "r"(a[0]), "r"(a[1]), "r"(a[2]), "r"(a[3]), "r"(b[0]), "r"(b[1]));
}

// ---------------------------------------------------------------------------
// GroupNorm (unchanged)
// ---------------------------------------------------------------------------
__global__ void gn_kernel(const float* __restrict__ x,
                          const float* __restrict__ gamma,
                          const float* __restrict__ beta,
                          float* __restrict__ h) {
    const int bg = blockIdx.x;
    const int b  = bg / NGROUPS;
    const int g  = bg % NGROUPS;
    const size_t base = ((size_t)b * CC + (size_t)g * CPG) * LL;
    const float* xp = x + base;

    float s = 0.f, s2 = 0.f;
    for (int i = threadIdx.x; i < GROUP_ELEMS; i += blockDim.x) {
        float v = xp[i];
        s += v; s2 += v * v;
    }
    __shared__ float red1[16], red2[16];
    s = warp_sum(s); s2 = warp_sum(s2);
    const int lane = threadIdx.x & 31, wid = threadIdx.x >> 5;
    if (lane == 0) { red1[wid] = s; red2[wid] = s2; }
    __syncthreads();
    if (wid == 0) {
        s  = (lane < 16) ? red1[lane] : 0.f;
        s2 = (lane < 16) ? red2[lane] : 0.f;
        s = warp_sum(s); s2 = warp_sum(s2);
        if (lane == 0) { red1[0] = s; red2[0] = s2; }
    }
    __syncthreads();
    const float mean = red1[0] * (1.0f / GROUP_ELEMS);
    const float var  = red2[0] * (1.0f / GROUP_ELEMS) - mean * mean;
    const float inv  = rsqrtf(var + EPS);

    float* hp = h + base;
    for (int i = threadIdx.x; i < GROUP_ELEMS; i += blockDim.x) {
        int c = g * CPG + i / LL;
        hp[i] = (xp[i] - mean) * inv * gamma[c] + beta[c];
    }
}

// ---------------------------------------------------------------------------
// Unified tf32 tensor-core GEMM.
//   out[b, m, n] = sum_k Aop[m,k] * Bop[n,k]   (+ epilogue)
// A_KMAJ: gmem A element (m,k) at A[k*lda + m]  (else A[m*lda + k])
// B_KMAJ: gmem B element (n,k) at B[k*ldb + n]  (else B[n*ldb + k])
// EPI: 0 plain, 1 +bias[m], 2 +bias[m]+X, 3 *scale
//
// Tile 128x128 x BK=32.  8 warps as 2(M) x 4(N); warp tile 64x32 = 4x4 m16n8k8.
// ---------------------------------------------------------------------------
#define BKK 32
#define KM_PAD 136   // 128 + 8 : fragment reads bank-conflict-free
#define MK_PAD 36    // 32 + 4

template<int EPI, bool A_KMAJ, bool B_KMAJ>
__global__ __launch_bounds__(256, 2)
void mma_gemm(const float* __restrict__ A, int lda, size_t sA,
              const float* __restrict__ B, int ldb, size_t sB,
              float* __restrict__ O, int ldo, size_t sO,
              int K,
              const float* __restrict__ bias,
              const float* __restrict__ X, size_t sX,
              float scale) {
    constexpr int ASZ = A_KMAJ ? BKK * KM_PAD : 128 * MK_PAD;
    constexpr int BSZ = B_KMAJ ? BKK * KM_PAD : 128 * MK_PAD;
    __shared__ float sAm[ASZ];
    __shared__ float sBm[BSZ];

    const int tid  = threadIdx.x;
    const int warp = tid >> 5, lane = tid & 31;
    const int wm = warp >> 2;        // 0..1
    const int wn = warp & 3;         // 0..3
    const int g  = lane >> 2;        // 0..7
    const int tig = lane & 3;        // 0..3
    const int mBase = blockIdx.y * 128;
    const int nBase = blockIdx.x * 128;

    const float* Ab = A + (size_t)blockIdx.z * sA;
    const float* Bb = B + (size_t)blockIdx.z * sB;

    float acc[4][4][4];
    #pragma unroll
    for (int i = 0; i < 4; i++)
        #pragma unroll
        for (int j = 0; j < 4; j++)
            #pragma unroll
            for (int r = 0; r < 4; r++) acc[i][j][r] = 0.f;

    for (int k0 = 0; k0 < K; k0 += BKK) {
        // ---- load + convert A tile ----
        if (A_KMAJ) {
            #pragma unroll
            for (int it = 0; it < 4; it++) {
                int s = tid + it * 256;
                int kk = s >> 5, mv = (s & 31) * 4;
                float4 t = *(const float4*)(Ab + (size_t)(k0 + kk) * lda + mBase + mv);
                float4 c = { to_tf32(t.x), to_tf32(t.y), to_tf32(t.z), to_tf32(t.w) };
                *(float4*)(sAm + kk * KM_PAD + mv) = c;
            }
        } else {
            #pragma unroll
            for (int it = 0; it < 4; it++) {
                int s = tid + it * 256;
                int m = s >> 3, kv = (s & 7) * 4;
                float4 t = *(const float4*)(Ab + (size_t)(mBase + m) * lda + k0 + kv);
                float4 c = { to_tf32(t.x), to_tf32(t.y), to_tf32(t.z), to_tf32(t.w) };
                *(float4*)(sAm + m * MK_PAD + kv) = c;
            }
        }
        // ---- load + convert B tile ----
        if (B_KMAJ) {
            #pragma unroll
            for (int it = 0; it < 4; it++) {
                int s = tid + it * 256;
                int kk = s >> 5, nv = (s & 31) * 4;
                float4 t = *(const float4*)(Bb + (size_t)(k0 + kk) * ldb + nBase + nv);
                float4 c = { to_tf32(t.x), to_tf32(t.y), to_tf32(t.z), to_tf32(t.w) };
                *(float4*)(sBm + kk * KM_PAD + nv) = c;
            }
        } else {
            #pragma unroll
            for (int it = 0; it < 4; it++) {
                int s = tid + it * 256;
                int n = s >> 3, kv = (s & 7) * 4;
                float4 t = *(const float4*)(Bb + (size_t)(nBase + n) * ldb + k0 + kv);
                float4 c = { to_tf32(t.x), to_tf32(t.y), to_tf32(t.z), to_tf32(t.w) };
                *(float4*)(sBm + n * MK_PAD + kv) = c;
            }
        }
        __syncthreads();

        #pragma unroll
        for (int ks = 0; ks < BKK / 8; ks++) {
            const int kb = ks * 8;
            uint32_t af[4][4], bf[4][2];
            #pragma unroll
            for (int mt = 0; mt < 4; mt++) {
                const int r0 = wm * 64 + mt * 16 + g;
                if (A_KMAJ) {
                    af[mt][0] = __float_as_uint(sAm[(kb + tig) * KM_PAD + r0]);
                    af[mt][1] = __float_as_uint(sAm[(kb + tig) * KM_PAD + r0 + 8]);
                    af[mt][2] = __float_as_uint(sAm[(kb + tig + 4) * KM_PAD + r0]);
                    af[mt][3] = __float_as_uint(sAm[(kb + tig + 4) * KM_PAD + r0 + 8]);
                } else {
                    af[mt][0] = __float_as_uint(sAm[r0 * MK_PAD + kb + tig]);
                    af[mt][1] = __float_as_uint(sAm[(r0 + 8) * MK_PAD + kb + tig]);
                    af[mt][2] = __float_as_uint(sAm[r0 * MK_PAD + kb + tig + 4]);
                    af[mt][3] = __float_as_uint(sAm[(r0 + 8) * MK_PAD + kb + tig + 4]);
                }
            }
            #pragma unroll
            for (int nt = 0; nt < 4; nt++) {
                const int c0 = wn * 32 + nt * 8 + g;
                if (B_KMAJ) {
                    bf[nt][0] = __float_as_uint(sBm[(kb + tig) * KM_PAD + c0]);
                    bf[nt][1] = __float_as_uint(sBm[(kb + tig + 4) * KM_PAD + c0]);
                } else {
                    bf[nt][0] = __float_as_uint(sBm[c0 * MK_PAD + kb + tig]);
                    bf[nt][1] = __float_as_uint(sBm[c0 * MK_PAD + kb + tig + 4]);
                }
            }
            #pragma unroll
            for (int mt = 0; mt < 4; mt++)
                #pragma unroll
                for (int nt = 0; nt < 4; nt++)
                    mma8(acc[mt][nt], af[mt], bf[nt]);
        }
        __syncthreads();
    }

    // ---- epilogue ----
    float* Ob = O + (size_t)blockIdx.z * sO;
    const float* Xb = (EPI == 2) ? (X + (size_t)blockIdx.z * sX) : nullptr;
    #pragma unroll
    for (int mt = 0; mt < 4; mt++) {
        const int r0 = mBase + wm * 64 + mt * 16 + g;
        #pragma unroll
        for (int half = 0; half < 2; half++) {
            const int row = r0 + half * 8;
            float bv = 0.f;
            if (EPI == 1 || EPI == 2) bv = bias[row];
            #pragma unroll
            for (int nt = 0; nt < 4; nt++) {
                const int col = nBase + wn * 32 + nt * 8 + tig * 2;
                float v0 = acc[mt][nt][half * 2 + 0];
                float v1 = acc[mt][nt][half * 2 + 1];
                if (EPI == 3) { v0 *= scale; v1 *= scale; }
                if (EPI == 1 || EPI == 2) { v0 += bv; v1 += bv; }
                if (EPI == 2) {
                    const float* xr = Xb + (size_t)row * ldo + col;
                    v0 += xr[0]; v1 += xr[1];
                }
                float2 st = { v0, v1 };
                *(float2*)(Ob + (size_t)row * ldo + col) = st;
            }
        }
    }
}

// ---------------------------------------------------------------------------
// Softmax (unchanged)
// ---------------------------------------------------------------------------
__global__ void softmax_kernel(float* __restrict__ w) {
    float* p = w + (size_t)blockIdx.x * LL;
    __shared__ float red[8];
    const int lane = threadIdx.x & 31, wid = threadIdx.x >> 5;

    float m = -1e30f;
    for (int i = threadIdx.x; i < LL; i += 256) m = fmaxf(m, p[i]);
    m = warp_max(m);
    if (lane == 0) red[wid] = m;
    __syncthreads();
    if (wid == 0) {
        m = (lane < 8) ? red[lane] : -1e30f;
        m = warp_max(m);
        if (lane == 0) red[0] = m;
    }
    __syncthreads();
    m = red[0];
    __syncthreads();

    float s = 0.f;
    for (int i = threadIdx.x; i < LL; i += 256) {
        float e = __expf(p[i] - m);
        p[i] = e;
        s += e;
    }
    s = warp_sum(s);
    if (lane == 0) red[wid] = s;
    __syncthreads();
    if (wid == 0) {
        s = (lane < 8) ? red[lane] : 0.f;
        s = warp_sum(s);
        if (lane == 0) red[0] = s;
    }
    __syncthreads();
    const float inv = 1.0f / red[0];
    for (int i = threadIdx.x; i < LL; i += 256) p[i] *= inv;
}

// ---------------------------------------------------------------------------
// Launch
// ---------------------------------------------------------------------------
extern "C" void kernel_launch(void* const* d_in, const int* in_sizes, int n_in,
                              void* d_out, int out_size) {
    const float* x        = (const float*)d_in[0];
    const float* gn_gamma = (const float*)d_in[1];
    const float* gn_beta  = (const float*)d_in[2];
    const float* Wq = (const float*)d_in[3];
    const float* bq = (const float*)d_in[4];
    const float* Wk = (const float*)d_in[5];
    const float* bk = (const float*)d_in[6];
    const float* Wv = (const float*)d_in[7];
    const float* bv = (const float*)d_in[8];
    const float* Wo = (const float*)d_in[9];
    const float* bo = (const float*)d_in[10];
    float* out = (float*)d_out;

    float *h, *q, *k, *v, *w, *a;
    cudaGetSymbolAddress((void**)&h, g_h);
    cudaGetSymbolAddress((void**)&q, g_q);
    cudaGetSymbolAddress((void**)&k, g_k);
    cudaGetSymbolAddress((void**)&v, g_v);
    cudaGetSymbolAddress((void**)&w, g_w);
    cudaGetSymbolAddress((void**)&a, g_a);

    const size_t CL = (size_t)CC * LL;
    const size_t LLs = (size_t)LL * LL;
    const float scale = 0.044194173824159216f;   // 1/sqrt(512)

    // 1. GroupNorm
    gn_kernel<<<BATCH * NGROUPS, 512>>>(x, gn_gamma, gn_beta, h);

    // 2. q,k,v projections: M=C(512), N=L(2048), K=C. A=W (m-major), B=h (k-major)
    dim3 gproj(LL / 128, CC / 128, BATCH);
    mma_gemm<1, false, true><<<gproj, 256>>>(Wq, CC, 0, h, LL, CL, q, LL, CL,
                                             CC, bq, nullptr, 0, 0.f);
    mma_gemm<1, false, true><<<gproj, 256>>>(Wk, CC, 0, h, LL, CL, k, LL, CL,
                                             CC, bk, nullptr, 0, 0.f);
    mma_gemm<1, false, true><<<gproj, 256>>>(Wv, CC, 0, h, LL, CL, v, LL, CL,
                                             CC, bv, nullptr, 0, 0.f);

    // 3. scores: M=N=L, K=C. A=q (k-major), B=k (k-major), *scale
    dim3 gqk(LL / 128, LL / 128, BATCH);
    mma_gemm<3, true, true><<<gqk, 256>>>(q, LL, CL, k, LL, CL, w, LL, LLs,
                                          CC, nullptr, nullptr, 0, scale);

    // 4. softmax rows
    softmax_kernel<<<BATCH * LL, 256>>>(w);

    // 5. a = attn @ v: M=C, N=L(i), K=L(j). A=v (m-major), B=w (n-major)
    dim3 gav(LL / 128, CC / 128, BATCH);
    mma_gemm<0, false, false><<<gav, 256>>>(v, LL, CL, w, LL, LLs, a, LL, CL,
                                            LL, nullptr, nullptr, 0, 0.f);

    // 6. out = x + Wo@a + bo
    mma_gemm<2, false, true><<<gproj, 256>>>(Wo, CC, 0, a, LL, CL, out, LL, CL,
                                             CC, bo, x, CL, 0.f);
}